// round 2
// baseline (speedup 1.0000x reference)
#include <cuda_runtime.h>
#include <math.h>

#define BB 4
#define CC 256
#define KIN 32
#define NN 4096

// ---------------- scratch (device globals; no allocation allowed) ------------
__device__ float d_fgh[BB][96][NN];                 // f(0..31), g(32..63), h(64..95)
__device__ float d_P[(size_t)BB * NN * NN];         // exp(s), 268 MB
__device__ float d_inv[BB][NN];                     // 1/rowsum
__device__ float d_opre[BB][KIN][NN];               // normalized o_pre

// ---------------- K1: projections f,g,h = W @ x + b --------------------------
__global__ __launch_bounds__(256) void k1_proj(
    const float* __restrict__ x,
    const float* __restrict__ Wf, const float* __restrict__ bf,
    const float* __restrict__ Wg, const float* __restrict__ bg,
    const float* __restrict__ Wh, const float* __restrict__ bh)
{
    int b  = blockIdx.y;
    int n0 = blockIdx.x * 128;
    int tid = threadIdx.x;
    __shared__ float xs[32][128];
    __shared__ float ws[96][36];   // padded pitch
    int nt = tid & 31;   // n quad index: n = nt*4..nt*4+3
    int jt = tid >> 5;   // 0..7 -> j group of 12

    float acc[12][4];
#pragma unroll
    for (int j = 0; j < 12; j++)
#pragma unroll
        for (int l = 0; l < 4; l++) acc[j][l] = 0.f;

    for (int c0 = 0; c0 < CC; c0 += 32) {
        __syncthreads();
        {   // load x chunk [32c][128n]
            int n4 = tid & 31, cbase = tid >> 5;
#pragma unroll
            for (int p = 0; p < 4; p++) {
                int cc = cbase + p * 8;
                float4 v = *(const float4*)&x[(((size_t)b * CC) + (c0 + cc)) * NN + n0 + n4 * 4];
                *(float4*)&xs[cc][n4 * 4] = v;
            }
        }
        {   // load W chunk [96j][32c]
            int c8 = tid & 7, jbase = tid >> 3;  // 32 j per pass
#pragma unroll
            for (int p = 0; p < 3; p++) {
                int j = jbase + p * 32;
                const float* Wp = (j < 32) ? Wf : ((j < 64) ? Wg : Wh);
                int row = j & 31;
                float4 v = *(const float4*)&Wp[row * CC + c0 + c8 * 4];
                ws[j][c8 * 4 + 0] = v.x; ws[j][c8 * 4 + 1] = v.y;
                ws[j][c8 * 4 + 2] = v.z; ws[j][c8 * 4 + 3] = v.w;
            }
        }
        __syncthreads();
#pragma unroll 4
        for (int cc = 0; cc < 32; cc++) {
            float4 xv = *(const float4*)&xs[cc][nt * 4];
#pragma unroll
            for (int jj = 0; jj < 12; jj++) {
                float w = ws[jt * 12 + jj][cc];
                acc[jj][0] += w * xv.x; acc[jj][1] += w * xv.y;
                acc[jj][2] += w * xv.z; acc[jj][3] += w * xv.w;
            }
        }
    }
#pragma unroll
    for (int jj = 0; jj < 12; jj++) {
        int j = jt * 12 + jj;
        float bias = (j < 32) ? bf[j] : ((j < 64) ? bg[j - 32] : bh[j - 64]);
        float4 v;
        v.x = acc[jj][0] + bias; v.y = acc[jj][1] + bias;
        v.z = acc[jj][2] + bias; v.w = acc[jj][3] + bias;
        *(float4*)&d_fgh[b][j][n0 + nt * 4] = v;
    }
}

// ---------------- K2: P[b][n][m] = exp( f(:,n) . g(:,m) ) --------------------
__global__ __launch_bounds__(256) void k2_qk()
{
    int b  = blockIdx.z;
    int n0 = blockIdx.y * 128;
    int m0 = blockIdx.x * 128;
    int tid = threadIdx.x;
    __shared__ float fs[32][128], gs[32][128];
    {
        int i4 = tid & 31, kb = tid >> 5;
#pragma unroll
        for (int p = 0; p < 4; p++) {
            int k = kb + p * 8;
            *(float4*)&fs[k][i4 * 4] = *(const float4*)&d_fgh[b][k][n0 + i4 * 4];
            *(float4*)&gs[k][i4 * 4] = *(const float4*)&d_fgh[b][32 + k][m0 + i4 * 4];
        }
    }
    __syncthreads();
    int tx = tid & 15, ty = tid >> 4;   // 16x16 threads, 8x8 microtile
    float acc[8][8];
#pragma unroll
    for (int i = 0; i < 8; i++)
#pragma unroll
        for (int j = 0; j < 8; j++) acc[i][j] = 0.f;

#pragma unroll 4
    for (int k = 0; k < 32; k++) {
        float4 a0 = *(const float4*)&fs[k][ty * 8];
        float4 a1 = *(const float4*)&fs[k][ty * 8 + 4];
        float4 b0 = *(const float4*)&gs[k][tx * 8];
        float4 b1 = *(const float4*)&gs[k][tx * 8 + 4];
        float av[8] = {a0.x, a0.y, a0.z, a0.w, a1.x, a1.y, a1.z, a1.w};
        float bv[8] = {b0.x, b0.y, b0.z, b0.w, b1.x, b1.y, b1.z, b1.w};
#pragma unroll
        for (int i = 0; i < 8; i++)
#pragma unroll
            for (int j = 0; j < 8; j++) acc[i][j] += av[i] * bv[j];
    }
    size_t base = (((size_t)b * NN) + n0 + ty * 8) * NN + m0 + tx * 8;
#pragma unroll
    for (int i = 0; i < 8; i++) {
        float4 v0, v1;
        v0.x = __expf(acc[i][0]); v0.y = __expf(acc[i][1]);
        v0.z = __expf(acc[i][2]); v0.w = __expf(acc[i][3]);
        v1.x = __expf(acc[i][4]); v1.y = __expf(acc[i][5]);
        v1.z = __expf(acc[i][6]); v1.w = __expf(acc[i][7]);
        *(float4*)&d_P[base + (size_t)i * NN]     = v0;
        *(float4*)&d_P[base + (size_t)i * NN + 4] = v1;
    }
}

// ---------------- K3: row sums -> 1/sum --------------------------------------
__global__ __launch_bounds__(256) void k3_rowsum()
{
    int b = blockIdx.y;
    int r = blockIdx.x * 8 + (threadIdx.x >> 5);
    int lane = threadIdx.x & 31;
    const float4* row = (const float4*)(d_P + (((size_t)b * NN) + r) * NN);
    float s = 0.f;
#pragma unroll 8
    for (int i = lane; i < NN / 4; i += 32) {
        float4 v = row[i];
        s += (v.x + v.y) + (v.z + v.w);
    }
#pragma unroll
    for (int off = 16; off > 0; off >>= 1) s += __shfl_xor_sync(0xffffffffu, s, off);
    if (lane == 0) d_inv[b][r] = 1.0f / s;
}

// ------- K4: normalize + transposed attn_map write + PV accumulate -----------
__global__ __launch_bounds__(256) void k4_av(float* __restrict__ attn)
{
    int b  = blockIdx.y;
    int r0 = blockIdx.x * 128;
    int tid = threadIdx.x;
    __shared__ float ps[128][65];      // [r][c], pitch 65: conflict-free column reads
    __shared__ float hs[32][64];       // [k][c], broadcast reads
    __shared__ float invr[128];
    if (tid < 128) invr[tid] = d_inv[b][r0 + tid];
    __syncthreads();

    int rt = tid & 31, kt = tid >> 5;       // PV map: r = rt + 32j, k = kt*4+kk
    int r4 = tid & 31, cwb = tid >> 5;      // attn-write map: r = r4*4+j, c = cwb + q*8
    float invA[4];
#pragma unroll
    for (int j = 0; j < 4; j++) invA[j] = invr[r4 * 4 + j];

    float acc[4][4];
#pragma unroll
    for (int i = 0; i < 4; i++)
#pragma unroll
        for (int j = 0; j < 4; j++) acc[i][j] = 0.f;

    float* attn_b = attn + (size_t)b * NN * NN;

    for (int cc = 0; cc < NN; cc += 64) {
        __syncthreads();
        {   // load P tile [128r][64c]
            int c4 = tid & 15, rb = tid >> 4;
#pragma unroll
            for (int p = 0; p < 8; p++) {
                int r = rb + p * 16;
                float4 v = *(const float4*)&d_P[(((size_t)b * NN) + (r0 + r)) * NN + cc + c4 * 4];
                ps[r][c4 * 4 + 0] = v.x; ps[r][c4 * 4 + 1] = v.y;
                ps[r][c4 * 4 + 2] = v.z; ps[r][c4 * 4 + 3] = v.w;
            }
        }
        {   // load h tile [32k][64c]
            int c4 = tid & 15, kb = tid >> 4;
#pragma unroll
            for (int p = 0; p < 2; p++) {
                int k = kb + p * 16;
                *(float4*)&hs[k][c4 * 4] = *(const float4*)&d_fgh[b][64 + k][cc + c4 * 4];
            }
        }
        __syncthreads();

        // attn_map[b][cc+c][r0 + r]  (contiguous over r -> coalesced)
#pragma unroll
        for (int q = 0; q < 8; q++) {
            int c = cwb + q * 8;
            float4 v;
            v.x = ps[r4 * 4 + 0][c] * invA[0];
            v.y = ps[r4 * 4 + 1][c] * invA[1];
            v.z = ps[r4 * 4 + 2][c] * invA[2];
            v.w = ps[r4 * 4 + 3][c] * invA[3];
            *(float4*)&attn_b[((size_t)(cc + c)) * NN + r0 + r4 * 4] = v;
        }

        // PV: acc[kk][jr] += h[kt*4+kk][c] * P[rt+32jr][c]
#pragma unroll 4
        for (int c = 0; c < 64; c++) {
            float a0 = ps[rt][c], a1 = ps[rt + 32][c];
            float a2 = ps[rt + 64][c], a3 = ps[rt + 96][c];
            float h0 = hs[kt * 4 + 0][c], h1 = hs[kt * 4 + 1][c];
            float h2 = hs[kt * 4 + 2][c], h3 = hs[kt * 4 + 3][c];
            acc[0][0] += h0 * a0; acc[0][1] += h0 * a1; acc[0][2] += h0 * a2; acc[0][3] += h0 * a3;
            acc[1][0] += h1 * a0; acc[1][1] += h1 * a1; acc[1][2] += h1 * a2; acc[1][3] += h1 * a3;
            acc[2][0] += h2 * a0; acc[2][1] += h2 * a1; acc[2][2] += h2 * a2; acc[2][3] += h2 * a3;
            acc[3][0] += h3 * a0; acc[3][1] += h3 * a1; acc[3][2] += h3 * a2; acc[3][3] += h3 * a3;
        }
    }

#pragma unroll
    for (int kk = 0; kk < 4; kk++)
#pragma unroll
        for (int jr = 0; jr < 4; jr++) {
            int r = rt + 32 * jr;
            d_opre[b][kt * 4 + kk][r0 + r] = acc[kk][jr] * invr[r];
        }
}

// ---------------- K5: y = gamma*(Wv @ o_pre + bv) + x ------------------------
__global__ __launch_bounds__(256) void k5_out(
    const float* __restrict__ x, const float* __restrict__ Wv,
    const float* __restrict__ bv, const float* __restrict__ gamma,
    float* __restrict__ y)
{
    int b  = blockIdx.y;
    int n0 = blockIdx.x * 128;
    int tid = threadIdx.x;
    __shared__ float os[32][128];
    {
        int n4 = tid & 31, kb = tid >> 5;
#pragma unroll
        for (int p = 0; p < 4; p++) {
            int k = kb + p * 8;
            *(float4*)&os[k][n4 * 4] = *(const float4*)&d_opre[b][k][n0 + n4 * 4];
        }
    }
    __syncthreads();
    int n  = tid & 127;
    int cg = tid >> 7;   // 0 or 1 -> c in [cg*128, cg*128+128)
    float ov[32];
#pragma unroll
    for (int k = 0; k < 32; k++) ov[k] = os[k][n];
    float gm = gamma[0];

    for (int ci = 0; ci < 128; ci++) {
        int c = cg * 128 + ci;
        float a = bv[c];
        const float4* wv = (const float4*)&Wv[c * 32];
#pragma unroll
        for (int q = 0; q < 8; q++) {
            float4 w = __ldg(&wv[q]);
            a += w.x * ov[q * 4 + 0] + w.y * ov[q * 4 + 1]
               + w.z * ov[q * 4 + 2] + w.w * ov[q * 4 + 3];
        }
        size_t idx = (((size_t)b * CC) + c) * NN + n0 + n;
        y[idx] = gm * a + x[idx];
    }
}

// ---------------- launch -----------------------------------------------------
extern "C" void kernel_launch(void* const* d_in, const int* in_sizes, int n_in,
                              void* d_out, int out_size)
{
    (void)in_sizes; (void)n_in; (void)out_size;
    const float* x     = (const float*)d_in[0];
    const float* Wf    = (const float*)d_in[1];
    const float* bf    = (const float*)d_in[2];
    const float* Wg    = (const float*)d_in[3];
    const float* bg    = (const float*)d_in[4];
    const float* Wh    = (const float*)d_in[5];
    const float* bh    = (const float*)d_in[6];
    const float* Wv    = (const float*)d_in[7];
    const float* bv    = (const float*)d_in[8];
    const float* gamma = (const float*)d_in[9];

    float* y    = (float*)d_out;
    float* attn = y + (size_t)BB * CC * NN;   // y first, then attn_map

    k1_proj  <<<dim3(NN / 128, BB),           256>>>(x, Wf, bf, Wg, bg, Wh, bh);
    k2_qk    <<<dim3(NN / 128, NN / 128, BB), 256>>>();
    k3_rowsum<<<dim3(NN / 8, BB),             256>>>();
    k4_av    <<<dim3(NN / 128, BB),           256>>>(attn);
    k5_out   <<<dim3(NN / 128, BB),           256>>>(x, Wv, bv, gamma, y);
}

// round 3
// speedup vs baseline: 1.1145x; 1.1145x over previous
#include <cuda_runtime.h>
#include <math.h>

#define BB 4
#define CC 256
#define KIN 32
#define NN 4096
#define CSPLIT 4

typedef unsigned long long ull;

// ---------------- packed fp32x2 helpers (Blackwell dual-rate fp32) -----------
__device__ __forceinline__ ull pack2(float lo, float hi) {
    ull r; asm("mov.b64 %0, {%1,%2};" : "=l"(r) : "f"(lo), "f"(hi)); return r;
}
__device__ __forceinline__ void unpack2(ull v, float& lo, float& hi) {
    asm("mov.b64 {%0,%1}, %2;" : "=f"(lo), "=f"(hi) : "l"(v));
}
__device__ __forceinline__ void fma2(ull& d, ull a, ull b) {
    asm("fma.rn.f32x2 %0, %1, %2, %0;" : "+l"(d) : "l"(a), "l"(b));
}

// ---------------- scratch (device globals; no allocation allowed) ------------
__device__ float d_fgh[BB][96][NN];                   // f(0..31), g(32..63), h(64..95)
__device__ float d_P[(size_t)BB * NN * NN];           // exp(s), 268 MB
__device__ float d_psum[BB][NN / 128][NN];            // per-mblock partial row sums
__device__ float d_inv[BB][NN];                       // 1/rowsum
__device__ float d_opre[CSPLIT][BB][KIN][NN];         // partial o_pre (pre-scaled by inv)

// ---------------- K1: projections f,g,h = W @ x + b --------------------------
__global__ __launch_bounds__(256) void k1_proj(
    const float* __restrict__ x,
    const float* __restrict__ Wf, const float* __restrict__ bf,
    const float* __restrict__ Wg, const float* __restrict__ bg,
    const float* __restrict__ Wh, const float* __restrict__ bh)
{
    int b  = blockIdx.y;
    int n0 = blockIdx.x * 128;
    int tid = threadIdx.x;
    __shared__ float xs[32][128];
    __shared__ float ws[96][36];
    int nt = tid & 31;
    int jt = tid >> 5;

    float acc[12][4];
#pragma unroll
    for (int j = 0; j < 12; j++)
#pragma unroll
        for (int l = 0; l < 4; l++) acc[j][l] = 0.f;

    for (int c0 = 0; c0 < CC; c0 += 32) {
        __syncthreads();
        {
            int n4 = tid & 31, cbase = tid >> 5;
#pragma unroll
            for (int p = 0; p < 4; p++) {
                int cc = cbase + p * 8;
                float4 v = *(const float4*)&x[(((size_t)b * CC) + (c0 + cc)) * NN + n0 + n4 * 4];
                *(float4*)&xs[cc][n4 * 4] = v;
            }
        }
        {
            int c8 = tid & 7, jbase = tid >> 3;
#pragma unroll
            for (int p = 0; p < 3; p++) {
                int j = jbase + p * 32;
                const float* Wp = (j < 32) ? Wf : ((j < 64) ? Wg : Wh);
                int row = j & 31;
                float4 v = *(const float4*)&Wp[row * CC + c0 + c8 * 4];
                ws[j][c8 * 4 + 0] = v.x; ws[j][c8 * 4 + 1] = v.y;
                ws[j][c8 * 4 + 2] = v.z; ws[j][c8 * 4 + 3] = v.w;
            }
        }
        __syncthreads();
#pragma unroll 4
        for (int cc = 0; cc < 32; cc++) {
            float4 xv = *(const float4*)&xs[cc][nt * 4];
#pragma unroll
            for (int jj = 0; jj < 12; jj++) {
                float w = ws[jt * 12 + jj][cc];
                acc[jj][0] += w * xv.x; acc[jj][1] += w * xv.y;
                acc[jj][2] += w * xv.z; acc[jj][3] += w * xv.w;
            }
        }
    }
#pragma unroll
    for (int jj = 0; jj < 12; jj++) {
        int j = jt * 12 + jj;
        float bias = (j < 32) ? bf[j] : ((j < 64) ? bg[j - 32] : bh[j - 64]);
        float4 v;
        v.x = acc[jj][0] + bias; v.y = acc[jj][1] + bias;
        v.z = acc[jj][2] + bias; v.w = acc[jj][3] + bias;
        *(float4*)&d_fgh[b][j][n0 + nt * 4] = v;
    }
}

// -------- K2: P = exp(f^T g), write P + per-mblock row-sum partials ----------
__global__ __launch_bounds__(256) void k2_qk()
{
    int b  = blockIdx.z;
    int n0 = blockIdx.y * 128;
    int mb = blockIdx.x;
    int m0 = mb * 128;
    int tid = threadIdx.x;
    __shared__ float fs[32][128], gs[32][128];
    {
        int i4 = tid & 31, kb = tid >> 5;
#pragma unroll
        for (int p = 0; p < 4; p++) {
            int k = kb + p * 8;
            *(float4*)&fs[k][i4 * 4] = *(const float4*)&d_fgh[b][k][n0 + i4 * 4];
            *(float4*)&gs[k][i4 * 4] = *(const float4*)&d_fgh[b][32 + k][m0 + i4 * 4];
        }
    }
    __syncthreads();
    int tx = tid & 15, ty = tid >> 4;
    ull acc2[8][4];
#pragma unroll
    for (int i = 0; i < 8; i++)
#pragma unroll
        for (int j = 0; j < 4; j++) acc2[i][j] = 0ULL;

#pragma unroll 4
    for (int k = 0; k < 32; k++) {
        float4 a0 = *(const float4*)&fs[k][ty * 8];
        float4 a1 = *(const float4*)&fs[k][ty * 8 + 4];
        const ull* gp = (const ull*)&gs[k][tx * 8];
        ull b0 = gp[0], b1 = gp[1], b2 = gp[2], b3 = gp[3];
        float av[8] = {a0.x, a0.y, a0.z, a0.w, a1.x, a1.y, a1.z, a1.w};
#pragma unroll
        for (int i = 0; i < 8; i++) {
            ull ap = pack2(av[i], av[i]);
            fma2(acc2[i][0], ap, b0);
            fma2(acc2[i][1], ap, b1);
            fma2(acc2[i][2], ap, b2);
            fma2(acc2[i][3], ap, b3);
        }
    }

    size_t base = (((size_t)b * NN) + n0 + ty * 8) * NN + m0 + tx * 8;
#pragma unroll
    for (int i = 0; i < 8; i++) {
        float e[8];
#pragma unroll
        for (int jp = 0; jp < 4; jp++) {
            float slo, shi;
            unpack2(acc2[i][jp], slo, shi);
            e[2 * jp]     = __expf(slo);
            e[2 * jp + 1] = __expf(shi);
        }
        float4 v0 = {e[0], e[1], e[2], e[3]};
        float4 v1 = {e[4], e[5], e[6], e[7]};
        *(float4*)&d_P[base + (size_t)i * NN]     = v0;
        *(float4*)&d_P[base + (size_t)i * NN + 4] = v1;

        float rs = ((e[0] + e[1]) + (e[2] + e[3])) + ((e[4] + e[5]) + (e[6] + e[7]));
#pragma unroll
        for (int off = 1; off < 16; off <<= 1)
            rs += __shfl_xor_sync(0xffffffffu, rs, off);
        if (tx == 0) d_psum[b][mb][n0 + ty * 8 + i] = rs;
    }
}

// ---------------- K3: reduce partials -> 1/sum -------------------------------
__global__ __launch_bounds__(256) void k3_inv()
{
    int b = blockIdx.y;
    int n = blockIdx.x * 256 + threadIdx.x;
    float s = 0.f;
#pragma unroll
    for (int mb = 0; mb < NN / 128; mb++) s += d_psum[b][mb][n];
    d_inv[b][n] = 1.0f / s;
}

// ------- K4: normalize + transposed attn_map write + PV accumulate -----------
// grid: (NN/128 r-tiles, CSPLIT c-parts, BB)
__global__ __launch_bounds__(256) void k4_av(float* __restrict__ attn)
{
    int b    = blockIdx.z;
    int part = blockIdx.y;
    int r0   = blockIdx.x * 128;
    int tid  = threadIdx.x;
    int lane = tid & 31;
    int w    = tid >> 5;

    __shared__ float ps[128][68];     // pitch 68: float4 STS aligned, 8B-pair LDS aligned
    __shared__ float hs[32][68];
    __shared__ float invr[128];

    if (tid < 128) invr[tid] = d_inv[b][r0 + tid];
    __syncthreads();

    float inv4[4];
#pragma unroll
    for (int s = 0; s < 4; s++) inv4[s] = invr[lane + 32 * s];

    ull acc[16];
#pragma unroll
    for (int i = 0; i < 16; i++) acc[i] = 0ULL;

    float* attn_b = attn + (size_t)b * NN * NN;
    const float* Pb = d_P + (size_t)b * NN * NN;

    int c4 = tid & 15, rb = tid >> 4;

    for (int it = 0; it < (NN / CSPLIT) / 64; it++) {
        int cc = part * (NN / CSPLIT) + it * 64;
        __syncthreads();
        // load P tile [128r][64c]
#pragma unroll
        for (int p = 0; p < 8; p++) {
            int r = rb + p * 16;
            float4 v = *(const float4*)&Pb[((size_t)(r0 + r)) * NN + cc + c4 * 4];
            *(float4*)&ps[r][c4 * 4] = v;
        }
        // load h tile [32k][64c]
#pragma unroll
        for (int p = 0; p < 2; p++) {
            int k = rb + p * 16;
            *(float4*)&hs[k][c4 * 4] = *(const float4*)&d_fgh[b][64 + k][cc + c4 * 4];
        }
        __syncthreads();

        // attn_map[b][cc+c][r0+r] : per warp 8 columns, per lane 4 r-strided rows
#pragma unroll
        for (int q = 0; q < 8; q++) {
            int c = w * 8 + q;
            size_t ob = ((size_t)(cc + c)) * NN + r0 + lane;
            attn_b[ob]      = ps[lane][c]      * inv4[0];
            attn_b[ob + 32] = ps[lane + 32][c] * inv4[1];
            attn_b[ob + 64] = ps[lane + 64][c] * inv4[2];
            attn_b[ob + 96] = ps[lane + 96][c] * inv4[3];
        }

        // PV: lane = k, warp covers rows w*16..w*16+15, pairs along c
#pragma unroll 4
        for (int t = 0; t < 32; t++) {
            ull hp = *(const ull*)&hs[lane][2 * t];
#pragma unroll
            for (int i = 0; i < 16; i++) {
                ull ap = *(const ull*)&ps[w * 16 + i][2 * t];
                fma2(acc[i], ap, hp);
            }
        }
    }

#pragma unroll
    for (int i = 0; i < 16; i++) {
        float lo, hi;
        unpack2(acc[i], lo, hi);
        int r = w * 16 + i;
        d_opre[part][b][lane][r0 + r] = (lo + hi) * invr[r];
    }
}

// ---------------- K5: y = gamma*(Wv @ sum(o_parts) + bv) + x -----------------
__global__ __launch_bounds__(256) void k5_out(
    const float* __restrict__ x, const float* __restrict__ Wv,
    const float* __restrict__ bv, const float* __restrict__ gamma,
    float* __restrict__ y)
{
    int b  = blockIdx.y;
    int n0 = blockIdx.x * 128;
    int tid = threadIdx.x;
    __shared__ float os[32][128];
    {
        int n4 = tid & 31, kb = tid >> 5;
#pragma unroll
        for (int p = 0; p < 4; p++) {
            int k = kb + p * 8;
            float4 a = *(const float4*)&d_opre[0][b][k][n0 + n4 * 4];
            float4 c1 = *(const float4*)&d_opre[1][b][k][n0 + n4 * 4];
            float4 c2 = *(const float4*)&d_opre[2][b][k][n0 + n4 * 4];
            float4 c3 = *(const float4*)&d_opre[3][b][k][n0 + n4 * 4];
            a.x += c1.x + c2.x + c3.x; a.y += c1.y + c2.y + c3.y;
            a.z += c1.z + c2.z + c3.z; a.w += c1.w + c2.w + c3.w;
            *(float4*)&os[k][n4 * 4] = a;
        }
    }
    __syncthreads();
    int n  = tid & 127;
    int cg = tid >> 7;
    float ov[32];
#pragma unroll
    for (int k = 0; k < 32; k++) ov[k] = os[k][n];
    float gm = gamma[0];

    for (int ci = 0; ci < 128; ci++) {
        int c = cg * 128 + ci;
        float a = bv[c];
        const float4* wv = (const float4*)&Wv[c * 32];
#pragma unroll
        for (int q = 0; q < 8; q++) {
            float4 wq = __ldg(&wv[q]);
            a += wq.x * ov[q * 4 + 0] + wq.y * ov[q * 4 + 1]
               + wq.z * ov[q * 4 + 2] + wq.w * ov[q * 4 + 3];
        }
        size_t idx = (((size_t)b * CC) + c) * NN + n0 + n;
        y[idx] = gm * a + x[idx];
    }
}

// ---------------- launch -----------------------------------------------------
extern "C" void kernel_launch(void* const* d_in, const int* in_sizes, int n_in,
                              void* d_out, int out_size)
{
    (void)in_sizes; (void)n_in; (void)out_size;
    const float* x     = (const float*)d_in[0];
    const float* Wf    = (const float*)d_in[1];
    const float* bf    = (const float*)d_in[2];
    const float* Wg    = (const float*)d_in[3];
    const float* bg    = (const float*)d_in[4];
    const float* Wh    = (const float*)d_in[5];
    const float* bh    = (const float*)d_in[6];
    const float* Wv    = (const float*)d_in[7];
    const float* bv    = (const float*)d_in[8];
    const float* gamma = (const float*)d_in[9];

    float* y    = (float*)d_out;
    float* attn = y + (size_t)BB * CC * NN;

    k1_proj<<<dim3(NN / 128, BB),              256>>>(x, Wf, bf, Wg, bg, Wh, bh);
    k2_qk  <<<dim3(NN / 128, NN / 128, BB),    256>>>();
    k3_inv <<<dim3(NN / 256, BB),              256>>>();
    k4_av  <<<dim3(NN / 128, CSPLIT, BB),      256>>>(attn);
    k5_out <<<dim3(NN / 128, BB),              256>>>(x, Wv, bv, gamma, y);
}

// round 7
// speedup vs baseline: 1.1544x; 1.0358x over previous
#include <cuda_runtime.h>
#include <math.h>

#define BB 4
#define CC 256
#define KIN 32
#define NN 4096
#define CSPLIT 8

typedef unsigned long long ull;

// ---------------- packed fp32x2 helpers (Blackwell dual-rate fp32) -----------
__device__ __forceinline__ ull pack2(float lo, float hi) {
    ull r; asm("mov.b64 %0, {%1,%2};" : "=l"(r) : "f"(lo), "f"(hi)); return r;
}
__device__ __forceinline__ void unpack2(ull v, float& lo, float& hi) {
    asm("mov.b64 {%0,%1}, %2;" : "=f"(lo), "=f"(hi) : "l"(v));
}
__device__ __forceinline__ void fma2(ull& d, ull a, ull b) {
    asm("fma.rn.f32x2 %0, %1, %2, %0;" : "+l"(d) : "l"(a), "l"(b));
}

// ---------------- scratch (device globals; no allocation allowed) ------------
__device__ float d_fgh[BB][96][NN];                   // f(0..31), g(32..63), h(64..95)
__device__ float d_psum[BB][NN / 128][NN];            // per-mblock partial row sums
__device__ float d_inv[BB][NN];                       // 1/rowsum
__device__ float d_opre[CSPLIT][BB][KIN][NN];         // partial o_pre (scaled by inv)

// ---------------- K1: projections f,g,h = W @ x + b --------------------------
__global__ __launch_bounds__(256) void k1_proj(
    const float* __restrict__ x,
    const float* __restrict__ Wf, const float* __restrict__ bf,
    const float* __restrict__ Wg, const float* __restrict__ bg,
    const float* __restrict__ Wh, const float* __restrict__ bh)
{
    int b  = blockIdx.y;
    int n0 = blockIdx.x * 128;
    int tid = threadIdx.x;
    __shared__ float xs[32][128];
    __shared__ float ws[96][36];
    int nt = tid & 31;
    int jt = tid >> 5;

    float acc[12][4];
#pragma unroll
    for (int j = 0; j < 12; j++)
#pragma unroll
        for (int l = 0; l < 4; l++) acc[j][l] = 0.f;

    for (int c0 = 0; c0 < CC; c0 += 32) {
        __syncthreads();
        {
            int n4 = tid & 31, cbase = tid >> 5;
#pragma unroll
            for (int p = 0; p < 4; p++) {
                int cc = cbase + p * 8;
                float4 v = *(const float4*)&x[(((size_t)b * CC) + (c0 + cc)) * NN + n0 + n4 * 4];
                *(float4*)&xs[cc][n4 * 4] = v;
            }
        }
        {
            int c8 = tid & 7, jbase = tid >> 3;
#pragma unroll
            for (int p = 0; p < 3; p++) {
                int j = jbase + p * 32;
                const float* Wp = (j < 32) ? Wf : ((j < 64) ? Wg : Wh);
                int row = j & 31;
                float4 v = *(const float4*)&Wp[row * CC + c0 + c8 * 4];
                ws[j][c8 * 4 + 0] = v.x; ws[j][c8 * 4 + 1] = v.y;
                ws[j][c8 * 4 + 2] = v.z; ws[j][c8 * 4 + 3] = v.w;
            }
        }
        __syncthreads();
#pragma unroll 4
        for (int cc = 0; cc < 32; cc++) {
            float4 xv = *(const float4*)&xs[cc][nt * 4];
#pragma unroll
            for (int jj = 0; jj < 12; jj++) {
                float w = ws[jt * 12 + jj][cc];
                acc[jj][0] += w * xv.x; acc[jj][1] += w * xv.y;
                acc[jj][2] += w * xv.z; acc[jj][3] += w * xv.w;
            }
        }
    }
#pragma unroll
    for (int jj = 0; jj < 12; jj++) {
        int j = jt * 12 + jj;
        float bias = (j < 32) ? bf[j] : ((j < 64) ? bg[j - 32] : bh[j - 64]);
        float4 v;
        v.x = acc[jj][0] + bias; v.y = acc[jj][1] + bias;
        v.z = acc[jj][2] + bias; v.w = acc[jj][3] + bias;
        *(float4*)&d_fgh[b][j][n0 + nt * 4] = v;
    }
}

// -------- K2s: rowsum pass: exp(f^T g) summed over m, NO P store -------------
__global__ __launch_bounds__(256) void k2s()
{
    int b  = blockIdx.z;
    int n0 = blockIdx.y * 128;
    int mb = blockIdx.x;
    int m0 = mb * 128;
    int tid = threadIdx.x;
    __shared__ float fs[32][128], gs[32][128];
    {
        int i4 = tid & 31, kb = tid >> 5;
#pragma unroll
        for (int p = 0; p < 4; p++) {
            int k = kb + p * 8;
            *(float4*)&fs[k][i4 * 4] = *(const float4*)&d_fgh[b][k][n0 + i4 * 4];
            *(float4*)&gs[k][i4 * 4] = *(const float4*)&d_fgh[b][32 + k][m0 + i4 * 4];
        }
    }
    __syncthreads();
    int tx = tid & 15, ty = tid >> 4;
    ull acc2[8][4];
#pragma unroll
    for (int i = 0; i < 8; i++)
#pragma unroll
        for (int j = 0; j < 4; j++) acc2[i][j] = 0ULL;

#pragma unroll 4
    for (int k = 0; k < 32; k++) {
        float4 a0 = *(const float4*)&fs[k][ty * 8];
        float4 a1 = *(const float4*)&fs[k][ty * 8 + 4];
        const ull* gp = (const ull*)&gs[k][tx * 8];
        ull b0 = gp[0], b1 = gp[1], b2 = gp[2], b3 = gp[3];
        float av[8] = {a0.x, a0.y, a0.z, a0.w, a1.x, a1.y, a1.z, a1.w};
#pragma unroll
        for (int i = 0; i < 8; i++) {
            ull ap = pack2(av[i], av[i]);
            fma2(acc2[i][0], ap, b0);
            fma2(acc2[i][1], ap, b1);
            fma2(acc2[i][2], ap, b2);
            fma2(acc2[i][3], ap, b3);
        }
    }

#pragma unroll
    for (int i = 0; i < 8; i++) {
        float e[8];
#pragma unroll
        for (int jp = 0; jp < 4; jp++) {
            float slo, shi;
            unpack2(acc2[i][jp], slo, shi);
            e[2 * jp]     = __expf(slo);
            e[2 * jp + 1] = __expf(shi);
        }
        float rs = ((e[0] + e[1]) + (e[2] + e[3])) + ((e[4] + e[5]) + (e[6] + e[7]));
#pragma unroll
        for (int off = 1; off < 16; off <<= 1)
            rs += __shfl_xor_sync(0xffffffffu, rs, off);
        if (tx == 0) d_psum[b][mb][n0 + ty * 8 + i] = rs;
    }
}

// ---------------- K3: reduce partials -> 1/sum -------------------------------
__global__ __launch_bounds__(256) void k3_inv()
{
    int b = blockIdx.y;
    int n = blockIdx.x * 256 + threadIdx.x;
    float s = 0.f;
#pragma unroll
    for (int mb = 0; mb < NN / 128; mb++) s += d_psum[b][mb][n];
    d_inv[b][n] = 1.0f / s;
}

// ------- K4f: recompute GEMM + exp + attn write (transposed) + PV ------------
// grid: (NN/128 r-tiles, CSPLIT c-parts, BB); block 256
__global__ __launch_bounds__(256) void k4f(float* __restrict__ attn)
{
    int b    = blockIdx.z;
    int part = blockIdx.y;
    int r0   = blockIdx.x * 128;
    int tid  = threadIdx.x;
    int lane = tid & 31;
    int w    = tid >> 5;

    __shared__ float fs[32][128];       // f tile, resident whole kernel
    __shared__ float gs[32][36];        // g chunk [32k][32c]
    __shared__ float hs[32][36];        // h chunk [32k][32c]
    __shared__ float es[128][36];       // exp tile [128r][32c]
    __shared__ float invr[128];

    if (tid < 128) invr[tid] = d_inv[b][r0 + tid];
    {   // load f tile [32k][128r]
        int i4 = tid & 31, kb = tid >> 5;
#pragma unroll
        for (int p = 0; p < 4; p++) {
            int k = kb + p * 8;
            *(float4*)&fs[k][i4 * 4] = *(const float4*)&d_fgh[b][k][r0 + i4 * 4];
        }
    }
    __syncthreads();

    float inv4[4];
#pragma unroll
    for (int s = 0; s < 4; s++) inv4[s] = invr[lane + 32 * s];

    int tx = tid & 7, ty = tid >> 3;    // GEMM micro: rows ty*4.., cols tx*4..
    int kl = tid >> 3, c4 = tid & 7;    // g/h loader: k=kl, cols c4*4..

    ull acc[16];
#pragma unroll
    for (int i = 0; i < 16; i++) acc[i] = 0ULL;

    float* attn_b = attn + (size_t)b * NN * NN;
    const int CB = NN / CSPLIT;         // 512 cols per block

    for (int it = 0; it < CB / 32; it++) {
        int cc = part * CB + it * 32;
        __syncthreads();   // prev PV/attn readers of es/hs done
        *(float4*)&gs[kl][c4 * 4] = *(const float4*)&d_fgh[b][32 + kl][cc + c4 * 4];
        *(float4*)&hs[kl][c4 * 4] = *(const float4*)&d_fgh[b][64 + kl][cc + c4 * 4];
        __syncthreads();

        // GEMM 128x32x32 -> exp -> es
        ull a2[4][2];
#pragma unroll
        for (int r = 0; r < 4; r++) { a2[r][0] = 0ULL; a2[r][1] = 0ULL; }
#pragma unroll 8
        for (int k = 0; k < 32; k++) {
            float4 fv = *(const float4*)&fs[k][ty * 4];
            const ull* gp = (const ull*)&gs[k][tx * 4];
            ull b0 = gp[0], b1 = gp[1];
            fma2(a2[0][0], pack2(fv.x, fv.x), b0); fma2(a2[0][1], pack2(fv.x, fv.x), b1);
            fma2(a2[1][0], pack2(fv.y, fv.y), b0); fma2(a2[1][1], pack2(fv.y, fv.y), b1);
            fma2(a2[2][0], pack2(fv.z, fv.z), b0); fma2(a2[2][1], pack2(fv.z, fv.z), b1);
            fma2(a2[3][0], pack2(fv.w, fv.w), b0); fma2(a2[3][1], pack2(fv.w, fv.w), b1);
        }
#pragma unroll
        for (int r = 0; r < 4; r++) {
            float s0, s1, s2, s3;
            unpack2(a2[r][0], s0, s1);
            unpack2(a2[r][1], s2, s3);
            float4 v = {__expf(s0), __expf(s1), __expf(s2), __expf(s3)};
            *(float4*)&es[ty * 4 + r][tx * 4] = v;
        }
        __syncthreads();

        // attn_map[b][cc+c][r0+r] = es[r][c]*inv[r] : warp w -> cols w*4..w*4+3
#pragma unroll
        for (int q = 0; q < 4; q++) {
            int c = w * 4 + q;
            size_t ob = ((size_t)(cc + c)) * NN + r0 + lane;
            attn_b[ob]      = es[lane][c]      * inv4[0];
            attn_b[ob + 32] = es[lane + 32][c] * inv4[1];
            attn_b[ob + 64] = es[lane + 64][c] * inv4[2];
            attn_b[ob + 96] = es[lane + 96][c] * inv4[3];
        }

        // PV: lane = k, warp w covers rows w*16..w*16+15, pairs along c
#pragma unroll 4
        for (int t = 0; t < 16; t++) {
            ull hp = *(const ull*)&hs[lane][2 * t];
#pragma unroll
            for (int i = 0; i < 16; i++) {
                ull ap = *(const ull*)&es[w * 16 + i][2 * t];
                fma2(acc[i], ap, hp);
            }
        }
    }

#pragma unroll
    for (int i = 0; i < 16; i++) {
        float lo, hi;
        unpack2(acc[i], lo, hi);
        int r = w * 16 + i;
        d_opre[part][b][lane][r0 + r] = (lo + hi) * invr[r];
    }
}

// ---------------- K5: y = gamma*(Wv @ sum(o_parts) + bv) + x -----------------
__global__ __launch_bounds__(256) void k5_out(
    const float* __restrict__ x, const float* __restrict__ Wv,
    const float* __restrict__ bv, const float* __restrict__ gamma,
    float* __restrict__ y)
{
    int b  = blockIdx.y;
    int n0 = blockIdx.x * 128;
    int tid = threadIdx.x;
    __shared__ float os[32][128];
    {
        int n4 = tid & 31, kb = tid >> 5;
#pragma unroll
        for (int p = 0; p < 4; p++) {
            int k = kb + p * 8;
            float4 a = *(const float4*)&d_opre[0][b][k][n0 + n4 * 4];
#pragma unroll
            for (int s = 1; s < CSPLIT; s++) {
                float4 c1 = *(const float4*)&d_opre[s][b][k][n0 + n4 * 4];
                a.x += c1.x; a.y += c1.y; a.z += c1.z; a.w += c1.w;
            }
            *(float4*)&os[k][n4 * 4] = a;
        }
    }
    __syncthreads();
    int n  = tid & 127;
    int cg = tid >> 7;
    float ov[32];
#pragma unroll
    for (int k = 0; k < 32; k++) ov[k] = os[k][n];
    float gm = gamma[0];

    for (int ci = 0; ci < 128; ci++) {
        int c = cg * 128 + ci;
        float a = bv[c];
        const float4* wv = (const float4*)&Wv[c * 32];
#pragma unroll
        for (int q = 0; q < 8; q++) {
            float4 wq = __ldg(&wv[q]);
            a += wq.x * ov[q * 4 + 0] + wq.y * ov[q * 4 + 1]
               + wq.z * ov[q * 4 + 2] + wq.w * ov[q * 4 + 3];
        }
        size_t idx = (((size_t)b * CC) + c) * NN + n0 + n;
        y[idx] = gm * a + x[idx];
    }
}

// ---------------- launch -----------------------------------------------------
extern "C" void kernel_launch(void* const* d_in, const int* in_sizes, int n_in,
                              void* d_out, int out_size)
{
    (void)in_sizes; (void)n_in; (void)out_size;
    const float* x     = (const float*)d_in[0];
    const float* Wf    = (const float*)d_in[1];
    const float* bf    = (const float*)d_in[2];
    const float* Wg    = (const float*)d_in[3];
    const float* bg    = (const float*)d_in[4];
    const float* Wh    = (const float*)d_in[5];
    const float* bh    = (const float*)d_in[6];
    const float* Wv    = (const float*)d_in[7];
    const float* bv    = (const float*)d_in[8];
    const float* gamma = (const float*)d_in[9];

    float* y    = (float*)d_out;
    float* attn = y + (size_t)BB * CC * NN;

    k1_proj<<<dim3(NN / 128, BB),           256>>>(x, Wf, bf, Wg, bg, Wh, bh);
    k2s    <<<dim3(NN / 128, NN / 128, BB), 256>>>();
    k3_inv <<<dim3(NN / 256, BB),           256>>>();
    k4f    <<<dim3(NN / 128, CSPLIT, BB),   256>>>(attn);
    k5_out <<<dim3(NN / 128, BB),           256>>>(x, Wv, bv, gamma, y);
}